// round 1
// baseline (speedup 1.0000x reference)
#include <cuda_runtime.h>
#include <math.h>

// Problem constants
#define ROWS   4096          // B*S = 2*2048
#define DMODEL 2048
#define NPROJ  8192          // 4*DMODEL
#define HEADS  16
#define HD     128
#define SEQ    2048
#define FP16MAX 65504.0f
#define RMS_EPS 1e-5f

// Scratch (allocation-free per harness rules)
__device__ float g_proj[(size_t)ROWS * NPROJ];   // 134 MB: [row][4H*hd]  q|k|v|g
__device__ float g_att [(size_t)ROWS * DMODEL];  // 34 MB: gated attention output

// ---------------------------------------------------------------------------
// Classic 128x128 SGEMM, BK=8, 8x8 per-thread register tile, 256 threads.
// A [M,K] row-major, B [K,N] row-major, C [M,N]. M,N,K multiples of 128/8.
// ---------------------------------------------------------------------------
__global__ __launch_bounds__(256, 2)
void sgemm128(const float* __restrict__ A, const float* __restrict__ B,
              float* __restrict__ C, int M, int N, int K)
{
    __shared__ float As[8 * 128];   // transposed: As[kk][m]
    __shared__ float Bs[8 * 128];   // Bs[kk][n]

    const int tid = threadIdx.x;
    const int tx = tid & 15, ty = tid >> 4;
    const int r0 = ty * 8, c0 = tx * 8;
    const int bm = blockIdx.y * 128, bn = blockIdx.x * 128;

    const int arow = tid >> 1;          // 0..127
    const int acol = (tid & 1) * 4;     // 0 or 4
    const int brow = tid >> 5;          // 0..7
    const int bcol = (tid & 31) * 4;    // 0..124

    float acc[8][8];
#pragma unroll
    for (int i = 0; i < 8; ++i)
#pragma unroll
        for (int j = 0; j < 8; ++j) acc[i][j] = 0.f;

    for (int k0 = 0; k0 < K; k0 += 8) {
        float4 a = *(const float4*)(A + (size_t)(bm + arow) * K + k0 + acol);
        As[(acol + 0) * 128 + arow] = a.x;
        As[(acol + 1) * 128 + arow] = a.y;
        As[(acol + 2) * 128 + arow] = a.z;
        As[(acol + 3) * 128 + arow] = a.w;
        *(float4*)(Bs + brow * 128 + bcol) =
            *(const float4*)(B + (size_t)(k0 + brow) * N + bn + bcol);
        __syncthreads();

#pragma unroll
        for (int kk = 0; kk < 8; ++kk) {
            float av[8], bv[8];
            *(float4*)&av[0] = *(const float4*)(As + kk * 128 + r0);
            *(float4*)&av[4] = *(const float4*)(As + kk * 128 + r0 + 4);
            *(float4*)&bv[0] = *(const float4*)(Bs + kk * 128 + c0);
            *(float4*)&bv[4] = *(const float4*)(Bs + kk * 128 + c0 + 4);
#pragma unroll
            for (int i = 0; i < 8; ++i)
#pragma unroll
                for (int j = 0; j < 8; ++j)
                    acc[i][j] = fmaf(av[i], bv[j], acc[i][j]);
        }
        __syncthreads();
    }

#pragma unroll
    for (int i = 0; i < 8; ++i) {
        float* crow = C + (size_t)(bm + r0 + i) * N + bn + c0;
        *(float4*)(crow)     = make_float4(acc[i][0], acc[i][1], acc[i][2], acc[i][3]);
        *(float4*)(crow + 4) = make_float4(acc[i][4], acc[i][5], acc[i][6], acc[i][7]);
    }
}

// ---------------------------------------------------------------------------
// Clamp + RMSNorm (no affine) over head_dim=128, in-place on g_proj.
// One warp per (row, head-slot). Slots 0..31 cover q heads 0-15 and k heads 0-15.
// ---------------------------------------------------------------------------
__global__ __launch_bounds__(256)
void rmsnorm_qk()
{
    const int gw = (blockIdx.x * blockDim.x + threadIdx.x) >> 5; // global warp
    const int lane = threadIdx.x & 31;
    const int row = gw >> 5;          // 0..4095
    const int slot = gw & 31;         // 0..31 -> cols slot*128
    if (row >= ROWS) return;

    float4* p = (float4*)(g_proj + (size_t)row * NPROJ + slot * HD);
    float4 v = p[lane];
    v.x = fminf(fmaxf(v.x, -FP16MAX), FP16MAX);
    v.y = fminf(fmaxf(v.y, -FP16MAX), FP16MAX);
    v.z = fminf(fmaxf(v.z, -FP16MAX), FP16MAX);
    v.w = fminf(fmaxf(v.w, -FP16MAX), FP16MAX);
    float ss = v.x * v.x + v.y * v.y + v.z * v.z + v.w * v.w;
#pragma unroll
    for (int off = 16; off; off >>= 1)
        ss += __shfl_xor_sync(0xffffffffu, ss, off);
    const float s = rsqrtf(ss * (1.0f / HD) + RMS_EPS);
    v.x *= s; v.y *= s; v.z *= s; v.w *= s;
    p[lane] = v;
}

// ---------------------------------------------------------------------------
// Flash attention, fp32 FFMA. Grid (qtile=16, head=16, batch=2), 256 threads.
// 128q x 128k tiles, head_dim 128. P overwrites the K smem buffer.
// Sigmoid gate fused in epilogue; writes g_att[row][h*128+d].
// ---------------------------------------------------------------------------
#define PAD 132
#define ATTN_SMEM (3 * 128 * PAD * 4)

__device__ __forceinline__ float redmax16(float v) {
    v = fmaxf(v, __shfl_xor_sync(0xffffffffu, v, 8));
    v = fmaxf(v, __shfl_xor_sync(0xffffffffu, v, 4));
    v = fmaxf(v, __shfl_xor_sync(0xffffffffu, v, 2));
    v = fmaxf(v, __shfl_xor_sync(0xffffffffu, v, 1));
    return v;
}
__device__ __forceinline__ float redsum16(float v) {
    v += __shfl_xor_sync(0xffffffffu, v, 8);
    v += __shfl_xor_sync(0xffffffffu, v, 4);
    v += __shfl_xor_sync(0xffffffffu, v, 2);
    v += __shfl_xor_sync(0xffffffffu, v, 1);
    return v;
}

__global__ __launch_bounds__(256, 1)
void attn_kernel()
{
    extern __shared__ float smem[];
    float* Qs = smem;                 // [d][q]  stride PAD
    float* Ks = smem + 128 * PAD;     // [d][k]  -> reused as Ps [k][q]
    float* Vs = smem + 2 * 128 * PAD; // [k][d]

    const int qt = blockIdx.x, h = blockIdx.y, b = blockIdx.z;
    const int tid = threadIdx.x;
    const int tx = tid & 15, ty = tid >> 4;
    const int r0 = ty * 8, c0 = tx * 8;
    const float scale = 0.08838834764831845f; // 1/sqrt(128)

    const float* Qg = g_proj + (size_t)(b * SEQ + qt * 128) * NPROJ + h * HD;
    const float* Kg = g_proj + (size_t)(b * SEQ) * NPROJ + (16 + h) * HD;
    const float* Vg = g_proj + (size_t)(b * SEQ) * NPROJ + (32 + h) * HD;
    const float* Gg = g_proj + (size_t)(b * SEQ + qt * 128) * NPROJ + (48 + h) * HD;

    // Load Q tile transposed (scaled)
#pragma unroll
    for (int it = 0; it < 16; ++it) {
        const int i = (tid >> 5) + it * 8;
        const int d = (tid & 31) * 4;
        float4 q = *(const float4*)(Qg + (size_t)i * NPROJ + d);
        Qs[(d + 0) * PAD + i] = q.x * scale;
        Qs[(d + 1) * PAD + i] = q.y * scale;
        Qs[(d + 2) * PAD + i] = q.z * scale;
        Qs[(d + 3) * PAD + i] = q.w * scale;
    }

    float m[8], l[8], o[8][8];
#pragma unroll
    for (int i = 0; i < 8; ++i) {
        m[i] = -INFINITY; l[i] = 0.f;
#pragma unroll
        for (int j = 0; j < 8; ++j) o[i][j] = 0.f;
    }

    for (int kt = 0; kt < 16; ++kt) {
        // Load K (transposed) and V (natural)
#pragma unroll
        for (int it = 0; it < 16; ++it) {
            const int i = (tid >> 5) + it * 8;
            const int d = (tid & 31) * 4;
            const size_t grow = (size_t)(kt * 128 + i) * NPROJ;
            float4 kv = *(const float4*)(Kg + grow + d);
            Ks[(d + 0) * PAD + i] = kv.x;
            Ks[(d + 1) * PAD + i] = kv.y;
            Ks[(d + 2) * PAD + i] = kv.z;
            Ks[(d + 3) * PAD + i] = kv.w;
            *(float4*)(Vs + i * PAD + d) = *(const float4*)(Vg + grow + d);
        }
        __syncthreads();

        // S = Q @ K^T (scaled)
        float s[8][8];
#pragma unroll
        for (int i = 0; i < 8; ++i)
#pragma unroll
            for (int j = 0; j < 8; ++j) s[i][j] = 0.f;
#pragma unroll 4
        for (int kk = 0; kk < 128; ++kk) {
            float av[8], bv[8];
            *(float4*)&av[0] = *(const float4*)(Qs + kk * PAD + r0);
            *(float4*)&av[4] = *(const float4*)(Qs + kk * PAD + r0 + 4);
            *(float4*)&bv[0] = *(const float4*)(Ks + kk * PAD + c0);
            *(float4*)&bv[4] = *(const float4*)(Ks + kk * PAD + c0 + 4);
#pragma unroll
            for (int i = 0; i < 8; ++i)
#pragma unroll
                for (int j = 0; j < 8; ++j)
                    s[i][j] = fmaf(av[i], bv[j], s[i][j]);
        }

        // Online softmax stats (reduce across the 16 tx lanes via shuffles)
#pragma unroll
        for (int i = 0; i < 8; ++i) {
            float mx = s[i][0];
#pragma unroll
            for (int j = 1; j < 8; ++j) mx = fmaxf(mx, s[i][j]);
            mx = redmax16(mx);
            const float mn = fmaxf(m[i], mx);
            const float corr = __expf(m[i] - mn);
            m[i] = mn;
            float rs = 0.f;
#pragma unroll
            for (int j = 0; j < 8; ++j) {
                s[i][j] = __expf(s[i][j] - mn);
                rs += s[i][j];
            }
            rs = redsum16(rs);
            l[i] = l[i] * corr + rs;
#pragma unroll
            for (int j = 0; j < 8; ++j) o[i][j] *= corr;
        }

        __syncthreads();   // everyone done reading Ks before it becomes Ps

        // Store P transposed: Ps[k][q]  (into Ks buffer)
#pragma unroll
        for (int j = 0; j < 8; ++j) {
            *(float4*)(Ks + (c0 + j) * PAD + r0) =
                make_float4(s[0][j], s[1][j], s[2][j], s[3][j]);
            *(float4*)(Ks + (c0 + j) * PAD + r0 + 4) =
                make_float4(s[4][j], s[5][j], s[6][j], s[7][j]);
        }
        __syncthreads();

        // O += P @ V
#pragma unroll 4
        for (int kk = 0; kk < 128; ++kk) {
            float av[8], bv[8];
            *(float4*)&av[0] = *(const float4*)(Ks + kk * PAD + r0);
            *(float4*)&av[4] = *(const float4*)(Ks + kk * PAD + r0 + 4);
            *(float4*)&bv[0] = *(const float4*)(Vs + kk * PAD + c0);
            *(float4*)&bv[4] = *(const float4*)(Vs + kk * PAD + c0 + 4);
#pragma unroll
            for (int i = 0; i < 8; ++i)
#pragma unroll
                for (int j = 0; j < 8; ++j)
                    o[i][j] = fmaf(av[i], bv[j], o[i][j]);
        }
        __syncthreads();   // before reloading Ks/Vs
    }

    // Epilogue: O/l, sigmoid gate, write g_att
#pragma unroll
    for (int i = 0; i < 8; ++i) {
        const float inv = 1.0f / l[i];
        float gv[8];
        *(float4*)&gv[0] = *(const float4*)(Gg + (size_t)(r0 + i) * NPROJ + c0);
        *(float4*)&gv[4] = *(const float4*)(Gg + (size_t)(r0 + i) * NPROJ + c0 + 4);
        float out[8];
#pragma unroll
        for (int j = 0; j < 8; ++j) {
            const float sg = 1.0f / (1.0f + __expf(-gv[j]));
            out[j] = sg * o[i][j] * inv;
        }
        float* orow = g_att + (size_t)(b * SEQ + qt * 128 + r0 + i) * DMODEL + h * HD + c0;
        *(float4*)(orow)     = make_float4(out[0], out[1], out[2], out[3]);
        *(float4*)(orow + 4) = make_float4(out[4], out[5], out[6], out[7]);
    }
}

// ---------------------------------------------------------------------------
extern "C" void kernel_launch(void* const* d_in, const int* in_sizes, int n_in,
                              void* d_out, int out_size)
{
    const float* hidden = (const float*)d_in[0];  // [2,2048,2048]
    const float* W_in   = (const float*)d_in[1];  // [2048,8192]
    const float* W_out  = (const float*)d_in[2];  // [2048,2048]
    float* out = (float*)d_out;                   // [2,2048,2048]

    float* proj = nullptr;
    float* att  = nullptr;
    cudaGetSymbolAddress((void**)&proj, g_proj);
    cudaGetSymbolAddress((void**)&att, g_att);

    cudaFuncSetAttribute(attn_kernel,
                         cudaFuncAttributeMaxDynamicSharedMemorySize, ATTN_SMEM);

    // 1) proj = hidden @ W_in  : [4096,2048] x [2048,8192]
    sgemm128<<<dim3(NPROJ / 128, ROWS / 128), 256>>>(hidden, W_in, proj,
                                                     ROWS, NPROJ, DMODEL);
    // 2) clamp + RMSNorm q,k in-place
    rmsnorm_qk<<<(ROWS * 32) / 8, 256>>>();
    // 3) attention + gate
    attn_kernel<<<dim3(16, HEADS, 2), 256, ATTN_SMEM>>>();
    // 4) out = att @ W_out : [4096,2048] x [2048,2048]
    sgemm128<<<dim3(DMODEL / 128, ROWS / 128), 256>>>(att, W_out, out,
                                                      ROWS, DMODEL, DMODEL);
}

// round 3
// speedup vs baseline: 1.6922x; 1.6922x over previous
#include <cuda_runtime.h>
#include <cuda_bf16.h>
#include <math.h>
#include <stdint.h>

// Problem constants
#define ROWS   4096          // B*S
#define DMODEL 2048
#define NPROJ  8192          // 4*DMODEL
#define HEADS  16
#define HD     128
#define SEQ    2048
#define FP16MAX 65504.0f
#define RMS_EPS 1e-5f

// ---------------- scratch (allocation-free) ----------------
__device__ float g_proj[(size_t)ROWS * NPROJ];             // 134 MB q|k|v|g
__device__ __nv_bfloat16 g_ahi [(size_t)ROWS * DMODEL];    // hidden hi
__device__ __nv_bfloat16 g_alo [(size_t)ROWS * DMODEL];    // hidden lo
__device__ __nv_bfloat16 g_winh[(size_t)NPROJ * DMODEL];   // W_in^T  [N,K]
__device__ __nv_bfloat16 g_winl[(size_t)NPROJ * DMODEL];
__device__ __nv_bfloat16 g_woh [(size_t)DMODEL * DMODEL];  // W_out^T [N,K]
__device__ __nv_bfloat16 g_wol [(size_t)DMODEL * DMODEL];
__device__ __nv_bfloat16 g_th  [(size_t)ROWS * DMODEL];    // attn out hi
__device__ __nv_bfloat16 g_tl  [(size_t)ROWS * DMODEL];    // attn out lo

// ---------------- PTX helpers (sm_80-portable only) ----------------
__device__ __forceinline__ uint32_t smem_u32(const void* p) {
    uint32_t a;
    asm("{ .reg .u64 t; cvta.to.shared.u64 t, %1; cvt.u32.u64 %0, t; }" : "=r"(a) : "l"(p));
    return a;
}
__device__ __forceinline__ void cp16(uint32_t saddr, const void* g) {
    asm volatile("cp.async.cg.shared.global [%0], [%1], 16;" :: "r"(saddr), "l"(g));
}
__device__ __forceinline__ void cp_commit() {
    asm volatile("cp.async.commit_group;" ::: "memory");
}
template <int N>
__device__ __forceinline__ void cp_wait() {
    asm volatile("cp.async.wait_group %0;" :: "n"(N) : "memory");
}
__device__ __forceinline__ void ldsm4(uint32_t* r, uint32_t a) {
    asm volatile("ldmatrix.sync.aligned.m8n8.x4.shared.b16 {%0,%1,%2,%3}, [%4];"
                 : "=r"(r[0]), "=r"(r[1]), "=r"(r[2]), "=r"(r[3]) : "r"(a));
}
__device__ __forceinline__ void mma16816(float* c, const uint32_t* a, const uint32_t* b) {
    asm volatile(
        "mma.sync.aligned.m16n8k16.row.col.f32.bf16.bf16.f32 "
        "{%0,%1,%2,%3}, {%4,%5,%6,%7}, {%8,%9}, {%0,%1,%2,%3};"
        : "+f"(c[0]), "+f"(c[1]), "+f"(c[2]), "+f"(c[3])
        : "r"(a[0]), "r"(a[1]), "r"(a[2]), "r"(a[3]), "r"(b[0]), "r"(b[1]));
}

// ---------------- prep: fp32 -> bf16 hi/lo (same layout) ----------------
__global__ void split_plain(const float* __restrict__ in,
                            __nv_bfloat16* __restrict__ hi,
                            __nv_bfloat16* __restrict__ lo, size_t n4)
{
    size_t i = (size_t)blockIdx.x * blockDim.x + threadIdx.x;
    size_t stride = (size_t)gridDim.x * blockDim.x;
    for (; i < n4; i += stride) {
        float4 x = ((const float4*)in)[i];
        __nv_bfloat16 h0 = __float2bfloat16(x.x), h1 = __float2bfloat16(x.y);
        __nv_bfloat16 h2 = __float2bfloat16(x.z), h3 = __float2bfloat16(x.w);
        __nv_bfloat16 l0 = __float2bfloat16(x.x - __bfloat162float(h0));
        __nv_bfloat16 l1 = __float2bfloat16(x.y - __bfloat162float(h1));
        __nv_bfloat16 l2 = __float2bfloat16(x.z - __bfloat162float(h2));
        __nv_bfloat16 l3 = __float2bfloat16(x.w - __bfloat162float(h3));
        ((__nv_bfloat162*)hi)[i * 2 + 0] = __nv_bfloat162(h0, h1);
        ((__nv_bfloat162*)hi)[i * 2 + 1] = __nv_bfloat162(h2, h3);
        ((__nv_bfloat162*)lo)[i * 2 + 0] = __nv_bfloat162(l0, l1);
        ((__nv_bfloat162*)lo)[i * 2 + 1] = __nv_bfloat162(l2, l3);
    }
}

// ---------------- prep: transpose+split: in [R,C] fp32 -> out [C,R] bf16 ----------
__global__ void transpose_split(const float* __restrict__ in,
                                __nv_bfloat16* __restrict__ hi,
                                __nv_bfloat16* __restrict__ lo, int R, int C)
{
    __shared__ float t[32][33];
    const int bx = blockIdx.x * 32, by = blockIdx.y * 32;
    const int tx = threadIdx.x, ty = threadIdx.y;
#pragma unroll
    for (int j = 0; j < 4; ++j)
        t[ty + 8 * j][tx] = in[(size_t)(by + ty + 8 * j) * C + bx + tx];
    __syncthreads();
#pragma unroll
    for (int j = 0; j < 4; ++j) {
        float v = t[tx][ty + 8 * j];
        __nv_bfloat16 h = __float2bfloat16(v);
        __nv_bfloat16 l = __float2bfloat16(v - __bfloat162float(h));
        size_t o = (size_t)(bx + ty + 8 * j) * R + by + tx;
        hi[o] = h;
        lo[o] = l;
    }
}

// ---------------- HMMA bf16x3 GEMM: C[M,N] = A[M,K] @ B[N,K]^T ----------------
// 128x128 block tile, BK=32, 8 warps (4m x 2n), warp tile 32x64.
// smem row = 32 bf16 data + pad -> 80 B (conflict-free ldmatrix phases).
#define BM 128
#define BN 128
#define BK 32
#define ROWB 80
#define TILEB (128 * ROWB)          // 10240 per matrix
#define STAGEB (4 * TILEB)          // Ahi,Alo,Bhi,Blo = 40960
#define GSMEM (2 * STAGEB)          // 81920

__global__ __launch_bounds__(256)
void gemm_hmma(const __nv_bfloat16* __restrict__ Ahi, const __nv_bfloat16* __restrict__ Alo,
               const __nv_bfloat16* __restrict__ Bhi, const __nv_bfloat16* __restrict__ Blo,
               float* __restrict__ C, int M, int N, int K, int rms_ncols)
{
    extern __shared__ char smraw[];
    const uint32_t sb = smem_u32(smraw);

    const int tid = threadIdx.x, wid = tid >> 5, lane = tid & 31;
    const int bm = blockIdx.y * BM, bn = blockIdx.x * BN;
    const int wm = wid >> 1, wn = wid & 1;

    const __nv_bfloat16* gsrc[4] = {
        Ahi + (size_t)bm * K, Alo + (size_t)bm * K,
        Bhi + (size_t)bn * K, Blo + (size_t)bn * K };

    const int nk = K / BK;

    auto stage_load = [&](int s, int kc) {
        const uint32_t base = sb + s * STAGEB;
        const size_t kofs = (size_t)kc * BK;
#pragma unroll
        for (int b = 0; b < 4; ++b) {
#pragma unroll
            for (int i = 0; i < 2; ++i) {
                const int v = tid + i * 256;      // 512 chunks of 16B
                const int row = v >> 2, c = v & 3;
                cp16(base + b * TILEB + row * ROWB + c * 16,
                     gsrc[b] + (size_t)row * K + kofs + c * 8);
            }
        }
    };

    float acc[16][4];                 // [mt*8 + bt*2 + half][4]
#pragma unroll
    for (int i = 0; i < 16; ++i)
#pragma unroll
        for (int j = 0; j < 4; ++j) acc[i][j] = 0.f;

    stage_load(0, 0); cp_commit();
    stage_load(1, 1); cp_commit();
    cp_wait<1>();
    __syncthreads();

    for (int c = 0; c < nk; ++c) {
        const int s = c & 1;
        const uint32_t Ah = sb + s * STAGEB;
        const uint32_t Al = Ah + TILEB;
        const uint32_t Bh = Ah + 2 * TILEB;
        const uint32_t Bl = Ah + 3 * TILEB;

#pragma unroll
        for (int ks = 0; ks < 2; ++ks) {
            uint32_t ah[2][4], al[2][4];
#pragma unroll
            for (int mt = 0; mt < 2; ++mt) {
                const uint32_t ro = (uint32_t)(wm * 32 + mt * 16 + (lane & 15)) * ROWB
                                  + ks * 32 + (lane >> 4) * 16;
                ldsm4(ah[mt], Ah + ro);
                ldsm4(al[mt], Al + ro);
            }
#pragma unroll
            for (int bt = 0; bt < 4; ++bt) {
                const uint32_t ro = (uint32_t)(wn * 64 + bt * 16 + (lane & 15)) * ROWB
                                  + ks * 32 + (lane >> 4) * 16;
                uint32_t bh[4], bl[4];
                ldsm4(bh, Bh + ro);
                ldsm4(bl, Bl + ro);
                const uint32_t b0h[2] = { bh[0], bh[2] }, b1h[2] = { bh[1], bh[3] };
                const uint32_t b0l[2] = { bl[0], bl[2] }, b1l[2] = { bl[1], bl[3] };
#pragma unroll
                for (int mt = 0; mt < 2; ++mt) {
                    mma16816(acc[mt * 8 + bt * 2 + 0], ah[mt], b0h);
                    mma16816(acc[mt * 8 + bt * 2 + 1], ah[mt], b1h);
                    mma16816(acc[mt * 8 + bt * 2 + 0], ah[mt], b0l);
                    mma16816(acc[mt * 8 + bt * 2 + 1], ah[mt], b1l);
                    mma16816(acc[mt * 8 + bt * 2 + 0], al[mt], b0h);
                    mma16816(acc[mt * 8 + bt * 2 + 1], al[mt], b1h);
                }
            }
        }

        __syncthreads();
        if (c + 2 < nk) {
            stage_load(s, c + 2);
            cp_commit();
            cp_wait<1>();
        } else {
            cp_wait<0>();
        }
        __syncthreads();
    }

    // ---- epilogue: optional fused clamp+RMSNorm over 128-col head blocks ----
    float* ssm = (float*)smraw;       // [2][128] partial sum-of-squares
    if (bn < rms_ncols) {
        float ssp[2][2] = { {0.f, 0.f}, {0.f, 0.f} };
#pragma unroll
        for (int mt = 0; mt < 2; ++mt)
#pragma unroll
            for (int bt = 0; bt < 4; ++bt)
#pragma unroll
                for (int half = 0; half < 2; ++half) {
                    float* a = acc[mt * 8 + bt * 2 + half];
#pragma unroll
                    for (int q = 0; q < 4; ++q) {
                        float v = fminf(fmaxf(a[q], -FP16MAX), FP16MAX);
                        a[q] = v;
                        ssp[mt][q >> 1] += v * v;
                    }
                }
#pragma unroll
        for (int mt = 0; mt < 2; ++mt)
#pragma unroll
            for (int hh = 0; hh < 2; ++hh) {
                float s0 = ssp[mt][hh];
                s0 += __shfl_xor_sync(0xffffffffu, s0, 1);
                s0 += __shfl_xor_sync(0xffffffffu, s0, 2);
                if ((lane & 3) == 0) {
                    const int row = wm * 32 + mt * 16 + (lane >> 2) + hh * 8;
                    ssm[wn * 128 + row] = s0;
                }
            }
        __syncthreads();
#pragma unroll
        for (int mt = 0; mt < 2; ++mt)
#pragma unroll
            for (int hh = 0; hh < 2; ++hh) {
                const int row = wm * 32 + mt * 16 + (lane >> 2) + hh * 8;
                const float tot = ssm[row] + ssm[128 + row];
                const float sc = rsqrtf(tot * (1.0f / 128.0f) + RMS_EPS);
#pragma unroll
                for (int bt = 0; bt < 4; ++bt)
#pragma unroll
                    for (int half = 0; half < 2; ++half) {
                        acc[mt * 8 + bt * 2 + half][hh * 2 + 0] *= sc;
                        acc[mt * 8 + bt * 2 + half][hh * 2 + 1] *= sc;
                    }
            }
    }

    // ---- store ----
#pragma unroll
    for (int mt = 0; mt < 2; ++mt)
#pragma unroll
        for (int bt = 0; bt < 4; ++bt)
#pragma unroll
            for (int half = 0; half < 2; ++half) {
                const int col = bn + wn * 64 + bt * 16 + half * 8 + (lane & 3) * 2;
                const int r0 = bm + wm * 32 + mt * 16 + (lane >> 2);
                float* a = acc[mt * 8 + bt * 2 + half];
                *(float2*)(C + (size_t)r0 * N + col)       = make_float2(a[0], a[1]);
                *(float2*)(C + (size_t)(r0 + 8) * N + col) = make_float2(a[2], a[3]);
            }
}

// ---------------- fp32 flash attention (writes bf16 hi/lo) ----------------
#define PAD 132
#define ATTN_SMEM (3 * 128 * PAD * 4)

__device__ __forceinline__ float redmax16(float v) {
    v = fmaxf(v, __shfl_xor_sync(0xffffffffu, v, 8));
    v = fmaxf(v, __shfl_xor_sync(0xffffffffu, v, 4));
    v = fmaxf(v, __shfl_xor_sync(0xffffffffu, v, 2));
    v = fmaxf(v, __shfl_xor_sync(0xffffffffu, v, 1));
    return v;
}
__device__ __forceinline__ float redsum16(float v) {
    v += __shfl_xor_sync(0xffffffffu, v, 8);
    v += __shfl_xor_sync(0xffffffffu, v, 4);
    v += __shfl_xor_sync(0xffffffffu, v, 2);
    v += __shfl_xor_sync(0xffffffffu, v, 1);
    return v;
}

__global__ __launch_bounds__(256, 1)
void attn_kernel()
{
    extern __shared__ float smem[];
    float* Qs = smem;
    float* Ks = smem + 128 * PAD;
    float* Vs = smem + 2 * 128 * PAD;

    const int qt = blockIdx.x, h = blockIdx.y, b = blockIdx.z;
    const int tid = threadIdx.x;
    const int tx = tid & 15, ty = tid >> 4;
    const int r0 = ty * 8, c0 = tx * 8;
    const float scale = 0.08838834764831845f;

    const float* Qg = g_proj + (size_t)(b * SEQ + qt * 128) * NPROJ + h * HD;
    const float* Kg = g_proj + (size_t)(b * SEQ) * NPROJ + (16 + h) * HD;
    const float* Vg = g_proj + (size_t)(b * SEQ) * NPROJ + (32 + h) * HD;
    const float* Gg = g_proj + (size_t)(b * SEQ + qt * 128) * NPROJ + (48 + h) * HD;

#pragma unroll
    for (int it = 0; it < 16; ++it) {
        const int i = (tid >> 5) + it * 8;
        const int d = (tid & 31) * 4;
        float4 q = *(const float4*)(Qg + (size_t)i * NPROJ + d);
        Qs[(d + 0) * PAD + i] = q.x * scale;
        Qs[(d + 1) * PAD + i] = q.y * scale;
        Qs[(d + 2) * PAD + i] = q.z * scale;
        Qs[(d + 3) * PAD + i] = q.w * scale;
    }

    float m[8], l[8], o[8][8];
#pragma unroll
    for (int i = 0; i < 8; ++i) {
        m[i] = -INFINITY; l[i] = 0.f;
#pragma unroll
        for (int j = 0; j < 8; ++j) o[i][j] = 0.f;
    }

    for (int kt = 0; kt < 16; ++kt) {
#pragma unroll
        for (int it = 0; it < 16; ++it) {
            const int i = (tid >> 5) + it * 8;
            const int d = (tid & 31) * 4;
            const size_t grow = (size_t)(kt * 128 + i) * NPROJ;
            float4 kv = *(const float4*)(Kg + grow + d);
            Ks[(d + 0) * PAD + i] = kv.x;
            Ks[(d + 1) * PAD + i] = kv.y;
            Ks[(d + 2) * PAD + i] = kv.z;
            Ks[(d + 3) * PAD + i] = kv.w;
            *(float4*)(Vs + i * PAD + d) = *(const float4*)(Vg + grow + d);
        }
        __syncthreads();

        float s[8][8];
#pragma unroll
        for (int i = 0; i < 8; ++i)
#pragma unroll
            for (int j = 0; j < 8; ++j) s[i][j] = 0.f;
#pragma unroll 4
        for (int kk = 0; kk < 128; ++kk) {
            float av[8], bv[8];
            *(float4*)&av[0] = *(const float4*)(Qs + kk * PAD + r0);
            *(float4*)&av[4] = *(const float4*)(Qs + kk * PAD + r0 + 4);
            *(float4*)&bv[0] = *(const float4*)(Ks + kk * PAD + c0);
            *(float4*)&bv[4] = *(const float4*)(Ks + kk * PAD + c0 + 4);
#pragma unroll
            for (int i = 0; i < 8; ++i)
#pragma unroll
                for (int j = 0; j < 8; ++j)
                    s[i][j] = fmaf(av[i], bv[j], s[i][j]);
        }

#pragma unroll
        for (int i = 0; i < 8; ++i) {
            float mx = s[i][0];
#pragma unroll
            for (int j = 1; j < 8; ++j) mx = fmaxf(mx, s[i][j]);
            mx = redmax16(mx);
            const float mn = fmaxf(m[i], mx);
            const float corr = __expf(m[i] - mn);
            m[i] = mn;
            float rs = 0.f;
#pragma unroll
            for (int j = 0; j < 8; ++j) {
                s[i][j] = __expf(s[i][j] - mn);
                rs += s[i][j];
            }
            rs = redsum16(rs);
            l[i] = l[i] * corr + rs;
#pragma unroll
            for (int j = 0; j < 8; ++j) o[i][j] *= corr;
        }

        __syncthreads();

#pragma unroll
        for (int j = 0; j < 8; ++j) {
            *(float4*)(Ks + (c0 + j) * PAD + r0) =
                make_float4(s[0][j], s[1][j], s[2][j], s[3][j]);
            *(float4*)(Ks + (c0 + j) * PAD + r0 + 4) =
                make_float4(s[4][j], s[5][j], s[6][j], s[7][j]);
        }
        __syncthreads();

#pragma unroll 4
        for (int kk = 0; kk < 128; ++kk) {
            float av[8], bv[8];
            *(float4*)&av[0] = *(const float4*)(Ks + kk * PAD + r0);
            *(float4*)&av[4] = *(const float4*)(Ks + kk * PAD + r0 + 4);
            *(float4*)&bv[0] = *(const float4*)(Vs + kk * PAD + c0);
            *(float4*)&bv[4] = *(const float4*)(Vs + kk * PAD + c0 + 4);
#pragma unroll
            for (int i = 0; i < 8; ++i)
#pragma unroll
                for (int j = 0; j < 8; ++j)
                    o[i][j] = fmaf(av[i], bv[j], o[i][j]);
        }
        __syncthreads();
    }

    // epilogue: O/l, sigmoid gate, write bf16 hi/lo for GEMM2
#pragma unroll
    for (int i = 0; i < 8; ++i) {
        const float inv = 1.0f / l[i];
        float gv[8];
        *(float4*)&gv[0] = *(const float4*)(Gg + (size_t)(r0 + i) * NPROJ + c0);
        *(float4*)&gv[4] = *(const float4*)(Gg + (size_t)(r0 + i) * NPROJ + c0 + 4);
        const size_t ob = (size_t)(b * SEQ + qt * 128 + r0 + i) * DMODEL + h * HD + c0;
#pragma unroll
        for (int j2 = 0; j2 < 4; ++j2) {
            float v0, v1;
            {
                const float sg0 = 1.0f / (1.0f + __expf(-gv[j2 * 2 + 0]));
                const float sg1 = 1.0f / (1.0f + __expf(-gv[j2 * 2 + 1]));
                v0 = sg0 * o[i][j2 * 2 + 0] * inv;
                v1 = sg1 * o[i][j2 * 2 + 1] * inv;
            }
            const __nv_bfloat16 h0 = __float2bfloat16(v0);
            const __nv_bfloat16 h1 = __float2bfloat16(v1);
            const __nv_bfloat16 l0 = __float2bfloat16(v0 - __bfloat162float(h0));
            const __nv_bfloat16 l1 = __float2bfloat16(v1 - __bfloat162float(h1));
            *(__nv_bfloat162*)(g_th + ob + j2 * 2) = __nv_bfloat162(h0, h1);
            *(__nv_bfloat162*)(g_tl + ob + j2 * 2) = __nv_bfloat162(l0, l1);
        }
    }
}

// ---------------------------------------------------------------------------
extern "C" void kernel_launch(void* const* d_in, const int* in_sizes, int n_in,
                              void* d_out, int out_size)
{
    const float* hidden = (const float*)d_in[0];
    const float* W_in   = (const float*)d_in[1];
    const float* W_out  = (const float*)d_in[2];
    float* out = (float*)d_out;

    float* proj;
    __nv_bfloat16 *ahi, *alo, *winh, *winl, *woh, *wol, *th, *tl;
    cudaGetSymbolAddress((void**)&proj, g_proj);
    cudaGetSymbolAddress((void**)&ahi,  g_ahi);
    cudaGetSymbolAddress((void**)&alo,  g_alo);
    cudaGetSymbolAddress((void**)&winh, g_winh);
    cudaGetSymbolAddress((void**)&winl, g_winl);
    cudaGetSymbolAddress((void**)&woh,  g_woh);
    cudaGetSymbolAddress((void**)&wol,  g_wol);
    cudaGetSymbolAddress((void**)&th,   g_th);
    cudaGetSymbolAddress((void**)&tl,   g_tl);

    cudaFuncSetAttribute(gemm_hmma,
                         cudaFuncAttributeMaxDynamicSharedMemorySize, GSMEM);
    cudaFuncSetAttribute(attn_kernel,
                         cudaFuncAttributeMaxDynamicSharedMemorySize, ATTN_SMEM);

    // prep
    split_plain<<<1024, 256>>>(hidden, ahi, alo, (size_t)ROWS * DMODEL / 4);
    transpose_split<<<dim3(NPROJ / 32, DMODEL / 32), dim3(32, 8)>>>(W_in, winh, winl,
                                                                    DMODEL, NPROJ);
    transpose_split<<<dim3(DMODEL / 32, DMODEL / 32), dim3(32, 8)>>>(W_out, woh, wol,
                                                                     DMODEL, DMODEL);

    // 1) proj = hidden @ W_in (clamp+rmsnorm fused for q,k cols [0,4096))
    gemm_hmma<<<dim3(NPROJ / BN, ROWS / BM), 256, GSMEM>>>(
        ahi, alo, winh, winl, proj, ROWS, NPROJ, DMODEL, 4096);

    // 2) attention + sigmoid gate (writes bf16 hi/lo)
    attn_kernel<<<dim3(16, HEADS, 2), 256, ATTN_SMEM>>>();

    // 3) out = att @ W_out
    gemm_hmma<<<dim3(DMODEL / BN, ROWS / BM), 256, GSMEM>>>(
        th, tl, woh, wol, out, ROWS, DMODEL, DMODEL, 0);
}

// round 4
// speedup vs baseline: 2.7107x; 1.6019x over previous
#include <cuda_runtime.h>
#include <cuda_bf16.h>
#include <math.h>
#include <stdint.h>

// Problem constants
#define ROWS   4096          // B*S
#define DMODEL 2048
#define NPROJ  8192          // 4*DMODEL
#define HEADS  16
#define HD     128
#define SEQ    2048
#define NB     2
#define FP16MAX 65504.0f
#define RMS_EPS 1e-5f
#define ATTN_SCALE 0.08838834764831845f

// ---------------- scratch (allocation-free) ----------------
#define HSD ((size_t)NB * HEADS * SEQ * HD)    // 8.39M elems
__device__ __nv_bfloat16 g_qh[HSD], g_ql[HSD];
__device__ __nv_bfloat16 g_kh[HSD], g_kl[HSD];
__device__ __nv_bfloat16 g_vh[HSD], g_vl[HSD];
__device__ float         g_gate[HSD];
__device__ __nv_bfloat16 g_ahi [(size_t)ROWS * DMODEL];    // hidden hi
__device__ __nv_bfloat16 g_alo [(size_t)ROWS * DMODEL];
__device__ __nv_bfloat16 g_winh[(size_t)NPROJ * DMODEL];   // W_in^T  [N,K]
__device__ __nv_bfloat16 g_winl[(size_t)NPROJ * DMODEL];
__device__ __nv_bfloat16 g_woh [(size_t)DMODEL * DMODEL];  // W_out^T [N,K]
__device__ __nv_bfloat16 g_wol [(size_t)DMODEL * DMODEL];
__device__ __nv_bfloat16 g_th  [(size_t)ROWS * DMODEL];    // attn out hi
__device__ __nv_bfloat16 g_tl  [(size_t)ROWS * DMODEL];

// ---------------- PTX helpers (sm_80-portable only) ----------------
__device__ __forceinline__ uint32_t smem_u32(const void* p) {
    uint32_t a;
    asm("{ .reg .u64 t; cvta.to.shared.u64 t, %1; cvt.u32.u64 %0, t; }" : "=r"(a) : "l"(p));
    return a;
}
__device__ __forceinline__ void cp16(uint32_t saddr, const void* g) {
    asm volatile("cp.async.cg.shared.global [%0], [%1], 16;" :: "r"(saddr), "l"(g));
}
__device__ __forceinline__ void cp_commit() {
    asm volatile("cp.async.commit_group;" ::: "memory");
}
template <int N>
__device__ __forceinline__ void cp_wait() {
    asm volatile("cp.async.wait_group %0;" :: "n"(N) : "memory");
}
__device__ __forceinline__ void ldsm4(uint32_t* r, uint32_t a) {
    asm volatile("ldmatrix.sync.aligned.m8n8.x4.shared.b16 {%0,%1,%2,%3}, [%4];"
                 : "=r"(r[0]), "=r"(r[1]), "=r"(r[2]), "=r"(r[3]) : "r"(a));
}
__device__ __forceinline__ void ldsm4t(uint32_t* r, uint32_t a) {
    asm volatile("ldmatrix.sync.aligned.m8n8.x4.trans.shared.b16 {%0,%1,%2,%3}, [%4];"
                 : "=r"(r[0]), "=r"(r[1]), "=r"(r[2]), "=r"(r[3]) : "r"(a));
}
__device__ __forceinline__ void mma16816(float* c, const uint32_t* a, const uint32_t* b) {
    asm volatile(
        "mma.sync.aligned.m16n8k16.row.col.f32.bf16.bf16.f32 "
        "{%0,%1,%2,%3}, {%4,%5,%6,%7}, {%8,%9}, {%0,%1,%2,%3};"
        : "+f"(c[0]), "+f"(c[1]), "+f"(c[2]), "+f"(c[3])
        : "r"(a[0]), "r"(a[1]), "r"(a[2]), "r"(a[3]), "r"(b[0]), "r"(b[1]));
}
__device__ __forceinline__ void split2(float x, float y, uint32_t& hi, uint32_t& lo) {
    __nv_bfloat162 h2 = __float22bfloat162_rn(make_float2(x, y));
    float hx = __bfloat162float(h2.x), hy = __bfloat162float(h2.y);
    __nv_bfloat162 l2 = __float22bfloat162_rn(make_float2(x - hx, y - hy));
    hi = *(uint32_t*)&h2;
    lo = *(uint32_t*)&l2;
}

// ---------------- prep kernels ----------------
__global__ void split_plain(const float* __restrict__ in,
                            __nv_bfloat16* __restrict__ hi,
                            __nv_bfloat16* __restrict__ lo, size_t n4)
{
    size_t i = (size_t)blockIdx.x * blockDim.x + threadIdx.x;
    size_t stride = (size_t)gridDim.x * blockDim.x;
    for (; i < n4; i += stride) {
        float4 x = ((const float4*)in)[i];
        __nv_bfloat16 h0 = __float2bfloat16(x.x), h1 = __float2bfloat16(x.y);
        __nv_bfloat16 h2 = __float2bfloat16(x.z), h3 = __float2bfloat16(x.w);
        __nv_bfloat16 l0 = __float2bfloat16(x.x - __bfloat162float(h0));
        __nv_bfloat16 l1 = __float2bfloat16(x.y - __bfloat162float(h1));
        __nv_bfloat16 l2 = __float2bfloat16(x.z - __bfloat162float(h2));
        __nv_bfloat16 l3 = __float2bfloat16(x.w - __bfloat162float(h3));
        ((__nv_bfloat162*)hi)[i * 2 + 0] = __nv_bfloat162(h0, h1);
        ((__nv_bfloat162*)hi)[i * 2 + 1] = __nv_bfloat162(h2, h3);
        ((__nv_bfloat162*)lo)[i * 2 + 0] = __nv_bfloat162(l0, l1);
        ((__nv_bfloat162*)lo)[i * 2 + 1] = __nv_bfloat162(l2, l3);
    }
}

__global__ void transpose_split(const float* __restrict__ in,
                                __nv_bfloat16* __restrict__ hi,
                                __nv_bfloat16* __restrict__ lo, int R, int C)
{
    __shared__ float t[32][33];
    const int bx = blockIdx.x * 32, by = blockIdx.y * 32;
    const int tx = threadIdx.x, ty = threadIdx.y;
#pragma unroll
    for (int j = 0; j < 4; ++j)
        t[ty + 8 * j][tx] = in[(size_t)(by + ty + 8 * j) * C + bx + tx];
    __syncthreads();
#pragma unroll
    for (int j = 0; j < 4; ++j) {
        float v = t[tx][ty + 8 * j];
        __nv_bfloat16 h = __float2bfloat16(v);
        __nv_bfloat16 l = __float2bfloat16(v - __bfloat162float(h));
        size_t o = (size_t)(bx + ty + 8 * j) * R + by + tx;
        hi[o] = h;
        lo[o] = l;
    }
}

// ---------------- HMMA bf16x3 GEMM: C[M,N] = A[M,K] @ B[N,K]^T ----------------
#define BM 128
#define BN 128
#define BK 32
#define ROWB 80
#define TILEB (128 * ROWB)
#define STAGEB (4 * TILEB)
#define GSMEM (2 * STAGEB)

__global__ __launch_bounds__(256)
void gemm_hmma(const __nv_bfloat16* __restrict__ Ahi, const __nv_bfloat16* __restrict__ Alo,
               const __nv_bfloat16* __restrict__ Bhi, const __nv_bfloat16* __restrict__ Blo,
               float* __restrict__ C, int M, int N, int K, int mode)
{
    extern __shared__ char smraw[];
    const uint32_t sb = smem_u32(smraw);

    const int tid = threadIdx.x, wid = tid >> 5, lane = tid & 31;
    const int bm = blockIdx.y * BM, bn = blockIdx.x * BN;
    const int wm = wid >> 1, wn = wid & 1;

    const __nv_bfloat16* gsrc[4] = {
        Ahi + (size_t)bm * K, Alo + (size_t)bm * K,
        Bhi + (size_t)bn * K, Blo + (size_t)bn * K };

    const int nk = K / BK;

    auto stage_load = [&](int s, int kc) {
        const uint32_t base = sb + s * STAGEB;
        const size_t kofs = (size_t)kc * BK;
#pragma unroll
        for (int b = 0; b < 4; ++b) {
#pragma unroll
            for (int i = 0; i < 2; ++i) {
                const int v = tid + i * 256;
                const int row = v >> 2, c = v & 3;
                cp16(base + b * TILEB + row * ROWB + c * 16,
                     gsrc[b] + (size_t)row * K + kofs + c * 8);
            }
        }
    };

    float acc[16][4];
#pragma unroll
    for (int i = 0; i < 16; ++i)
#pragma unroll
        for (int j = 0; j < 4; ++j) acc[i][j] = 0.f;

    stage_load(0, 0); cp_commit();
    stage_load(1, 1); cp_commit();
    cp_wait<1>();
    __syncthreads();

    for (int c = 0; c < nk; ++c) {
        const int s = c & 1;
        const uint32_t Ah = sb + s * STAGEB;
        const uint32_t Al = Ah + TILEB;
        const uint32_t Bh = Ah + 2 * TILEB;
        const uint32_t Bl = Ah + 3 * TILEB;

#pragma unroll
        for (int ks = 0; ks < 2; ++ks) {
            uint32_t ah[2][4], al[2][4];
#pragma unroll
            for (int mt = 0; mt < 2; ++mt) {
                const uint32_t ro = (uint32_t)(wm * 32 + mt * 16 + (lane & 15)) * ROWB
                                  + ks * 32 + (lane >> 4) * 16;
                ldsm4(ah[mt], Ah + ro);
                ldsm4(al[mt], Al + ro);
            }
#pragma unroll
            for (int bt = 0; bt < 4; ++bt) {
                const uint32_t ro = (uint32_t)(wn * 64 + bt * 16 + (lane & 15)) * ROWB
                                  + ks * 32 + (lane >> 4) * 16;
                uint32_t bh[4], bl[4];
                ldsm4(bh, Bh + ro);
                ldsm4(bl, Bl + ro);
                const uint32_t b0h[2] = { bh[0], bh[2] }, b1h[2] = { bh[1], bh[3] };
                const uint32_t b0l[2] = { bl[0], bl[2] }, b1l[2] = { bl[1], bl[3] };
#pragma unroll
                for (int mt = 0; mt < 2; ++mt) {
                    mma16816(acc[mt * 8 + bt * 2 + 0], ah[mt], b0h);
                    mma16816(acc[mt * 8 + bt * 2 + 1], ah[mt], b1h);
                    mma16816(acc[mt * 8 + bt * 2 + 0], ah[mt], b0l);
                    mma16816(acc[mt * 8 + bt * 2 + 1], ah[mt], b1l);
                    mma16816(acc[mt * 8 + bt * 2 + 0], al[mt], b0h);
                    mma16816(acc[mt * 8 + bt * 2 + 1], al[mt], b1h);
                }
            }
        }

        __syncthreads();
        if (c + 2 < nk) {
            stage_load(s, c + 2);
            cp_commit();
            cp_wait<1>();
        } else {
            cp_wait<0>();
        }
        __syncthreads();
    }

    const int group = bn >> 11;       // 0=q 1=k 2=v 3=g (mode 1 only)

    // ---- fused clamp+RMSNorm for q,k (mode 1) ----
    float* ssm = (float*)smraw;
    if (mode && group < 2) {
        float ssp[2][2] = { {0.f, 0.f}, {0.f, 0.f} };
#pragma unroll
        for (int mt = 0; mt < 2; ++mt)
#pragma unroll
            for (int bt = 0; bt < 4; ++bt)
#pragma unroll
                for (int half = 0; half < 2; ++half) {
                    float* a = acc[mt * 8 + bt * 2 + half];
#pragma unroll
                    for (int q = 0; q < 4; ++q) {
                        float v = fminf(fmaxf(a[q], -FP16MAX), FP16MAX);
                        a[q] = v;
                        ssp[mt][q >> 1] += v * v;
                    }
                }
#pragma unroll
        for (int mt = 0; mt < 2; ++mt)
#pragma unroll
            for (int hh = 0; hh < 2; ++hh) {
                float s0 = ssp[mt][hh];
                s0 += __shfl_xor_sync(0xffffffffu, s0, 1);
                s0 += __shfl_xor_sync(0xffffffffu, s0, 2);
                if ((lane & 3) == 0) {
                    const int row = wm * 32 + mt * 16 + (lane >> 2) + hh * 8;
                    ssm[wn * 128 + row] = s0;
                }
            }
        __syncthreads();
        const float post = (group == 0) ? ATTN_SCALE : 1.0f;
#pragma unroll
        for (int mt = 0; mt < 2; ++mt)
#pragma unroll
            for (int hh = 0; hh < 2; ++hh) {
                const int row = wm * 32 + mt * 16 + (lane >> 2) + hh * 8;
                const float tot = ssm[row] + ssm[128 + row];
                const float sc = rsqrtf(tot * (1.0f / 128.0f) + RMS_EPS) * post;
#pragma unroll
                for (int bt = 0; bt < 4; ++bt)
#pragma unroll
                    for (int half = 0; half < 2; ++half) {
                        acc[mt * 8 + bt * 2 + half][hh * 2 + 0] *= sc;
                        acc[mt * 8 + bt * 2 + half][hh * 2 + 1] *= sc;
                    }
            }
    }

    if (mode) {
        // store q/k/v as bf16 hi/lo in [b][h][s][d]; gate as fp32
        const int hh = (bn >> 7) & 15;
        __nv_bfloat16* dsth = (group == 0) ? g_qh : (group == 1) ? g_kh : g_vh;
        __nv_bfloat16* dstl = (group == 0) ? g_ql : (group == 1) ? g_kl : g_vl;
#pragma unroll
        for (int mt = 0; mt < 2; ++mt)
#pragma unroll
            for (int bt = 0; bt < 4; ++bt)
#pragma unroll
                for (int half = 0; half < 2; ++half) {
                    const int d = wn * 64 + bt * 16 + half * 8 + (lane & 3) * 2;
                    float* a = acc[mt * 8 + bt * 2 + half];
#pragma unroll
                    for (int rr = 0; rr < 2; ++rr) {
                        const int row = bm + wm * 32 + mt * 16 + (lane >> 2) + rr * 8;
                        const int bb = row >> 11, s = row & 2047;
                        const size_t idx = ((size_t)(bb * HEADS + hh) * SEQ + s) * HD + d;
                        const float x = a[rr * 2 + 0], y = a[rr * 2 + 1];
                        if (group == 3) {
                            *(float2*)(g_gate + idx) = make_float2(x, y);
                        } else {
                            uint32_t hi, lo;
                            split2(x, y, hi, lo);
                            *(uint32_t*)(dsth + idx) = hi;
                            *(uint32_t*)(dstl + idx) = lo;
                        }
                    }
                }
    } else {
#pragma unroll
        for (int mt = 0; mt < 2; ++mt)
#pragma unroll
            for (int bt = 0; bt < 4; ++bt)
#pragma unroll
                for (int half = 0; half < 2; ++half) {
                    const int col = bn + wn * 64 + bt * 16 + half * 8 + (lane & 3) * 2;
                    const int r0 = bm + wm * 32 + mt * 16 + (lane >> 2);
                    float* a = acc[mt * 8 + bt * 2 + half];
                    *(float2*)(C + (size_t)r0 * N + col)       = make_float2(a[0], a[1]);
                    *(float2*)(C + (size_t)(r0 + 8) * N + col) = make_float2(a[2], a[3]);
                }
    }
}

// ---------------- HMMA bf16x3 flash attention ----------------
// 8 warps x 16 q-rows = 128 q rows per CTA; kv tiles of 64; grid (16, 16, 2).
#define AROWB 272                       // 128 bf16 + 8 pad = 272 B rows
#define QTILE_B (128 * AROWB)           // 34816
#define KVROWS 64
#define KVARR_B (KVROWS * AROWB)        // 17408
#define STAGE_ATT (4 * KVARR_B)         // 69632
#define ATTN_SMEM (2 * QTILE_B + 2 * STAGE_ATT)   // 208896

__global__ __launch_bounds__(256, 1)
void attn_hmma()
{
    extern __shared__ char smraw[];
    const uint32_t sb = smem_u32(smraw);

    const int tid = threadIdx.x, w = tid >> 5, lane = tid & 31;
    const int qt = blockIdx.x, h = blockIdx.y, b = blockIdx.z;
    const size_t hb = ((size_t)b * HEADS + h) * SEQ;

    const __nv_bfloat16* Qh_g = g_qh + (hb + qt * 128) * HD;
    const __nv_bfloat16* Ql_g = g_ql + (hb + qt * 128) * HD;
    const __nv_bfloat16* Kh_g = g_kh + hb * HD;
    const __nv_bfloat16* Kl_g = g_kl + hb * HD;
    const __nv_bfloat16* Vh_g = g_vh + hb * HD;
    const __nv_bfloat16* Vl_g = g_vl + hb * HD;

    auto loadKV = [&](int s, int kt) {
        const uint32_t base = sb + 2 * QTILE_B + s * STAGE_ATT;
        const size_t kv0 = (size_t)kt * KVROWS;
#pragma unroll
        for (int i = 0; i < 4; ++i) {
            const int v = tid + i * 256;
            const int row = v >> 4, c = v & 15;
            const uint32_t so = base + row * AROWB + c * 16;
            const size_t go = (kv0 + row) * HD + c * 8;
            cp16(so,               Kh_g + go);
            cp16(so + KVARR_B,     Kl_g + go);
            cp16(so + 2 * KVARR_B, Vh_g + go);
            cp16(so + 3 * KVARR_B, Vl_g + go);
        }
    };

    // Q load + first KV stage = group 0
#pragma unroll
    for (int i = 0; i < 8; ++i) {
        const int v = tid + i * 256;
        const int row = v >> 4, c = v & 15;
        const uint32_t so = row * AROWB + c * 16;
        const size_t go = (size_t)row * HD + c * 8;
        cp16(sb + so,           Qh_g + go);
        cp16(sb + QTILE_B + so, Ql_g + go);
    }
    loadKV(0, 0); cp_commit();
    loadKV(1, 1); cp_commit();
    cp_wait<1>();
    __syncthreads();

    float oacc[16][4];
#pragma unroll
    for (int i = 0; i < 16; ++i)
#pragma unroll
        for (int j = 0; j < 4; ++j) oacc[i][j] = 0.f;
    float m0 = -INFINITY, m1 = -INFINITY, l0 = 0.f, l1 = 0.f;

    const int nkt = SEQ / KVROWS;   // 32
    for (int c = 0; c < nkt; ++c) {
        const int s = c & 1;
        const uint32_t kbase = sb + 2 * QTILE_B + s * STAGE_ATT;

        // ---- S = Q @ K^T (bf16x3) ----
        float sacc[8][4];
#pragma unroll
        for (int i = 0; i < 8; ++i)
#pragma unroll
            for (int j = 0; j < 4; ++j) sacc[i][j] = 0.f;

#pragma unroll
        for (int kt = 0; kt < 8; ++kt) {
            uint32_t ah[4], al[4];
            const uint32_t qo = (uint32_t)(w * 16 + (lane & 15)) * AROWB
                              + kt * 32 + (lane >> 4) * 16;
            ldsm4(ah, sb + qo);
            ldsm4(al, sb + QTILE_B + qo);
#pragma unroll
            for (int g = 0; g < 4; ++g) {
                const uint32_t ko = kbase + (uint32_t)(g * 16 + (lane & 15)) * AROWB
                                  + kt * 32 + (lane >> 4) * 16;
                uint32_t bh[4], bl[4];
                ldsm4(bh, ko);
                ldsm4(bl, ko + KVARR_B);
                const uint32_t b0h[2] = { bh[0], bh[2] }, b1h[2] = { bh[1], bh[3] };
                const uint32_t b0l[2] = { bl[0], bl[2] }, b1l[2] = { bl[1], bl[3] };
                mma16816(sacc[2 * g + 0], ah, b0h);
                mma16816(sacc[2 * g + 1], ah, b1h);
                mma16816(sacc[2 * g + 0], ah, b0l);
                mma16816(sacc[2 * g + 1], ah, b1l);
                mma16816(sacc[2 * g + 0], al, b0h);
                mma16816(sacc[2 * g + 1], al, b1h);
            }
        }

        // ---- online softmax ----
        float mx0 = -INFINITY, mx1 = -INFINITY;
#pragma unroll
        for (int j = 0; j < 8; ++j) {
            mx0 = fmaxf(mx0, fmaxf(sacc[j][0], sacc[j][1]));
            mx1 = fmaxf(mx1, fmaxf(sacc[j][2], sacc[j][3]));
        }
        mx0 = fmaxf(mx0, __shfl_xor_sync(0xffffffffu, mx0, 1));
        mx0 = fmaxf(mx0, __shfl_xor_sync(0xffffffffu, mx0, 2));
        mx1 = fmaxf(mx1, __shfl_xor_sync(0xffffffffu, mx1, 1));
        mx1 = fmaxf(mx1, __shfl_xor_sync(0xffffffffu, mx1, 2));
        const float mn0 = fmaxf(m0, mx0), mn1 = fmaxf(m1, mx1);
        const float corr0 = __expf(m0 - mn0), corr1 = __expf(m1 - mn1);
        m0 = mn0; m1 = mn1;
        float rs0 = 0.f, rs1 = 0.f;
#pragma unroll
        for (int j = 0; j < 8; ++j) {
            sacc[j][0] = __expf(sacc[j][0] - mn0);
            sacc[j][1] = __expf(sacc[j][1] - mn0);
            sacc[j][2] = __expf(sacc[j][2] - mn1);
            sacc[j][3] = __expf(sacc[j][3] - mn1);
            rs0 += sacc[j][0] + sacc[j][1];
            rs1 += sacc[j][2] + sacc[j][3];
        }
        rs0 += __shfl_xor_sync(0xffffffffu, rs0, 1);
        rs0 += __shfl_xor_sync(0xffffffffu, rs0, 2);
        rs1 += __shfl_xor_sync(0xffffffffu, rs1, 1);
        rs1 += __shfl_xor_sync(0xffffffffu, rs1, 2);
        l0 = l0 * corr0 + rs0;
        l1 = l1 * corr1 + rs1;
#pragma unroll
        for (int n = 0; n < 16; ++n) {
            oacc[n][0] *= corr0; oacc[n][1] *= corr0;
            oacc[n][2] *= corr1; oacc[n][3] *= corr1;
        }

        // ---- P (C-frag) -> A-frag hi/lo, in registers ----
        uint32_t pah[4][4], pal[4][4];
#pragma unroll
        for (int kc = 0; kc < 4; ++kc) {
            split2(sacc[2 * kc][0],     sacc[2 * kc][1],     pah[kc][0], pal[kc][0]);
            split2(sacc[2 * kc][2],     sacc[2 * kc][3],     pah[kc][1], pal[kc][1]);
            split2(sacc[2 * kc + 1][0], sacc[2 * kc + 1][1], pah[kc][2], pal[kc][2]);
            split2(sacc[2 * kc + 1][2], sacc[2 * kc + 1][3], pah[kc][3], pal[kc][3]);
        }

        // ---- O += P @ V (bf16x3, V via ldmatrix.trans) ----
#pragma unroll
        for (int kc = 0; kc < 4; ++kc) {
#pragma unroll
            for (int g2 = 0; g2 < 8; ++g2) {
                const uint32_t vo = kbase + 2 * KVARR_B
                                  + (uint32_t)(kc * 16 + (lane & 15)) * AROWB
                                  + (g2 * 16 + (lane >> 4) * 8) * 2;
                uint32_t vh[4], vl[4];
                ldsm4t(vh, vo);
                ldsm4t(vl, vo + KVARR_B);
                const uint32_t b0h[2] = { vh[0], vh[1] }, b1h[2] = { vh[2], vh[3] };
                const uint32_t b0l[2] = { vl[0], vl[1] }, b1l[2] = { vl[2], vl[3] };
                mma16816(oacc[2 * g2 + 0], pah[kc], b0h);
                mma16816(oacc[2 * g2 + 1], pah[kc], b1h);
                mma16816(oacc[2 * g2 + 0], pah[kc], b0l);
                mma16816(oacc[2 * g2 + 1], pah[kc], b1l);
                mma16816(oacc[2 * g2 + 0], pal[kc], b0h);
                mma16816(oacc[2 * g2 + 1], pal[kc], b1h);
            }
        }

        __syncthreads();
        if (c + 2 < nkt) {
            loadKV(s, c + 2);
            cp_commit();
            cp_wait<1>();
        } else {
            cp_wait<0>();
        }
        __syncthreads();
    }

    // ---- epilogue: O/l, sigmoid gate, split hi/lo for GEMM2 ----
    const float inv0 = 1.0f / l0, inv1 = 1.0f / l1;
    const int r0 = w * 16 + (lane >> 2);
#pragma unroll
    for (int n = 0; n < 16; ++n) {
        const int d = n * 8 + (lane & 3) * 2;
#pragma unroll
        for (int rr = 0; rr < 2; ++rr) {
            const int qrow = qt * 128 + r0 + rr * 8;
            const float inv = rr ? inv1 : inv0;
            const float2 gv = *(const float2*)(g_gate + (hb + qrow) * HD + d);
            const float sg0 = 1.0f / (1.0f + __expf(-gv.x));
            const float sg1 = 1.0f / (1.0f + __expf(-gv.y));
            const float x = sg0 * oacc[n][rr * 2 + 0] * inv;
            const float y = sg1 * oacc[n][rr * 2 + 1] * inv;
            uint32_t hi, lo;
            split2(x, y, hi, lo);
            const size_t o = (size_t)(b * SEQ + qrow) * DMODEL + h * HD + d;
            *(uint32_t*)(g_th + o) = hi;
            *(uint32_t*)(g_tl + o) = lo;
        }
    }
}

// ---------------------------------------------------------------------------
extern "C" void kernel_launch(void* const* d_in, const int* in_sizes, int n_in,
                              void* d_out, int out_size)
{
    const float* hidden = (const float*)d_in[0];
    const float* W_in   = (const float*)d_in[1];
    const float* W_out  = (const float*)d_in[2];
    float* out = (float*)d_out;

    __nv_bfloat16 *ahi, *alo, *winh, *winl, *woh, *wol, *th, *tl;
    cudaGetSymbolAddress((void**)&ahi,  g_ahi);
    cudaGetSymbolAddress((void**)&alo,  g_alo);
    cudaGetSymbolAddress((void**)&winh, g_winh);
    cudaGetSymbolAddress((void**)&winl, g_winl);
    cudaGetSymbolAddress((void**)&woh,  g_woh);
    cudaGetSymbolAddress((void**)&wol,  g_wol);
    cudaGetSymbolAddress((void**)&th,   g_th);
    cudaGetSymbolAddress((void**)&tl,   g_tl);

    cudaFuncSetAttribute(gemm_hmma,
                         cudaFuncAttributeMaxDynamicSharedMemorySize, GSMEM);
    cudaFuncSetAttribute(attn_hmma,
                         cudaFuncAttributeMaxDynamicSharedMemorySize, ATTN_SMEM);

    // prep
    split_plain<<<1024, 256>>>(hidden, ahi, alo, (size_t)ROWS * DMODEL / 4);
    transpose_split<<<dim3(NPROJ / 32, DMODEL / 32), dim3(32, 8)>>>(W_in, winh, winl,
                                                                    DMODEL, NPROJ);
    transpose_split<<<dim3(DMODEL / 32, DMODEL / 32), dim3(32, 8)>>>(W_out, woh, wol,
                                                                     DMODEL, DMODEL);

    // 1) proj GEMM -> writes q/k/v bf16 hi/lo (+rmsnorm+scale) and gate fp32
    gemm_hmma<<<dim3(NPROJ / BN, ROWS / BM), 256, GSMEM>>>(
        ahi, alo, winh, winl, nullptr, ROWS, NPROJ, DMODEL, 1);

    // 2) HMMA flash attention + sigmoid gate -> g_th/g_tl
    attn_hmma<<<dim3(16, HEADS, NB), 256, ATTN_SMEM>>>();

    // 3) out = att @ W_out
    gemm_hmma<<<dim3(DMODEL / BN, ROWS / BM), 256, GSMEM>>>(
        th, tl, woh, wol, out, ROWS, DMODEL, DMODEL, 0);
}

// round 5
// speedup vs baseline: 2.7576x; 1.0173x over previous
#include <cuda_runtime.h>
#include <cuda_bf16.h>
#include <math.h>
#include <stdint.h>

// Problem constants
#define ROWS   4096          // B*S
#define DMODEL 2048
#define NPROJ  8192          // 4*DMODEL
#define HEADS  16
#define HD     128
#define SEQ    2048
#define NB     2
#define FP16MAX 65504.0f
#define RMS_EPS 1e-5f
#define ATTN_SCALE 0.08838834764831845f

// ---------------- scratch (allocation-free) ----------------
#define HSD ((size_t)NB * HEADS * SEQ * HD)    // 8.39M elems
__device__ __nv_bfloat16 g_qh[HSD], g_ql[HSD];
__device__ __nv_bfloat16 g_kh[HSD], g_kl[HSD];
__device__ __nv_bfloat16 g_vh[HSD], g_vl[HSD];
__device__ float         g_gate[HSD];
__device__ __nv_bfloat16 g_ahi [(size_t)ROWS * DMODEL];    // hidden hi
__device__ __nv_bfloat16 g_alo [(size_t)ROWS * DMODEL];
__device__ __nv_bfloat16 g_winh[(size_t)NPROJ * DMODEL];   // W_in^T  [N,K]
__device__ __nv_bfloat16 g_winl[(size_t)NPROJ * DMODEL];
__device__ __nv_bfloat16 g_woh [(size_t)DMODEL * DMODEL];  // W_out^T [N,K]
__device__ __nv_bfloat16 g_wol [(size_t)DMODEL * DMODEL];
__device__ __nv_bfloat16 g_th  [(size_t)ROWS * DMODEL];    // attn out hi
__device__ __nv_bfloat16 g_tl  [(size_t)ROWS * DMODEL];

// ---------------- PTX helpers (sm_80-portable only) ----------------
__device__ __forceinline__ uint32_t smem_u32(const void* p) {
    uint32_t a;
    asm("{ .reg .u64 t; cvta.to.shared.u64 t, %1; cvt.u32.u64 %0, t; }" : "=r"(a) : "l"(p));
    return a;
}
__device__ __forceinline__ void cp16(uint32_t saddr, const void* g) {
    asm volatile("cp.async.cg.shared.global [%0], [%1], 16;" :: "r"(saddr), "l"(g));
}
__device__ __forceinline__ void cp_commit() {
    asm volatile("cp.async.commit_group;" ::: "memory");
}
template <int N>
__device__ __forceinline__ void cp_wait() {
    asm volatile("cp.async.wait_group %0;" :: "n"(N) : "memory");
}
__device__ __forceinline__ void ldsm4(uint32_t* r, uint32_t a) {
    asm volatile("ldmatrix.sync.aligned.m8n8.x4.shared.b16 {%0,%1,%2,%3}, [%4];"
                 : "=r"(r[0]), "=r"(r[1]), "=r"(r[2]), "=r"(r[3]) : "r"(a));
}
__device__ __forceinline__ void ldsm4t(uint32_t* r, uint32_t a) {
    asm volatile("ldmatrix.sync.aligned.m8n8.x4.trans.shared.b16 {%0,%1,%2,%3}, [%4];"
                 : "=r"(r[0]), "=r"(r[1]), "=r"(r[2]), "=r"(r[3]) : "r"(a));
}
__device__ __forceinline__ void mma16816(float* c, const uint32_t* a, const uint32_t* b) {
    asm volatile(
        "mma.sync.aligned.m16n8k16.row.col.f32.bf16.bf16.f32 "
        "{%0,%1,%2,%3}, {%4,%5,%6,%7}, {%8,%9}, {%0,%1,%2,%3};"
        : "+f"(c[0]), "+f"(c[1]), "+f"(c[2]), "+f"(c[3])
        : "r"(a[0]), "r"(a[1]), "r"(a[2]), "r"(a[3]), "r"(b[0]), "r"(b[1]));
}
__device__ __forceinline__ void split2(float x, float y, uint32_t& hi, uint32_t& lo) {
    __nv_bfloat162 h2 = __float22bfloat162_rn(make_float2(x, y));
    float hx = __bfloat162float(h2.x), hy = __bfloat162float(h2.y);
    __nv_bfloat162 l2 = __float22bfloat162_rn(make_float2(x - hx, y - hy));
    hi = *(uint32_t*)&h2;
    lo = *(uint32_t*)&l2;
}

// ---------------- prep kernels ----------------
__global__ void split_plain(const float* __restrict__ in,
                            __nv_bfloat16* __restrict__ hi,
                            __nv_bfloat16* __restrict__ lo, size_t n4)
{
    size_t i = (size_t)blockIdx.x * blockDim.x + threadIdx.x;
    size_t stride = (size_t)gridDim.x * blockDim.x;
    for (; i < n4; i += stride) {
        float4 x = ((const float4*)in)[i];
        __nv_bfloat16 h0 = __float2bfloat16(x.x), h1 = __float2bfloat16(x.y);
        __nv_bfloat16 h2 = __float2bfloat16(x.z), h3 = __float2bfloat16(x.w);
        __nv_bfloat16 l0 = __float2bfloat16(x.x - __bfloat162float(h0));
        __nv_bfloat16 l1 = __float2bfloat16(x.y - __bfloat162float(h1));
        __nv_bfloat16 l2 = __float2bfloat16(x.z - __bfloat162float(h2));
        __nv_bfloat16 l3 = __float2bfloat16(x.w - __bfloat162float(h3));
        ((__nv_bfloat162*)hi)[i * 2 + 0] = __nv_bfloat162(h0, h1);
        ((__nv_bfloat162*)hi)[i * 2 + 1] = __nv_bfloat162(h2, h3);
        ((__nv_bfloat162*)lo)[i * 2 + 0] = __nv_bfloat162(l0, l1);
        ((__nv_bfloat162*)lo)[i * 2 + 1] = __nv_bfloat162(l2, l3);
    }
}

__global__ void transpose_split(const float* __restrict__ in,
                                __nv_bfloat16* __restrict__ hi,
                                __nv_bfloat16* __restrict__ lo, int R, int C)
{
    __shared__ float t[32][33];
    const int bx = blockIdx.x * 32, by = blockIdx.y * 32;
    const int tx = threadIdx.x, ty = threadIdx.y;
#pragma unroll
    for (int j = 0; j < 4; ++j)
        t[ty + 8 * j][tx] = in[(size_t)(by + ty + 8 * j) * C + bx + tx];
    __syncthreads();
#pragma unroll
    for (int j = 0; j < 4; ++j) {
        float v = t[tx][ty + 8 * j];
        __nv_bfloat16 h = __float2bfloat16(v);
        __nv_bfloat16 l = __float2bfloat16(v - __bfloat162float(h));
        size_t o = (size_t)(bx + ty + 8 * j) * R + by + tx;
        hi[o] = h;
        lo[o] = l;
    }
}

// ---------------- HMMA bf16x3 GEMM: C[M,N] = A[M,K] @ B[N,K]^T ----------------
#define BM 128
#define BN 128
#define BK 32
#define ROWB 80
#define TILEB (128 * ROWB)
#define STAGEB (4 * TILEB)
#define GSMEM (2 * STAGEB)

__global__ __launch_bounds__(256)
void gemm_hmma(const __nv_bfloat16* __restrict__ Ahi, const __nv_bfloat16* __restrict__ Alo,
               const __nv_bfloat16* __restrict__ Bhi, const __nv_bfloat16* __restrict__ Blo,
               float* __restrict__ C, int M, int N, int K, int mode)
{
    extern __shared__ char smraw[];
    const uint32_t sb = smem_u32(smraw);

    const int tid = threadIdx.x, wid = tid >> 5, lane = tid & 31;
    const int bm = blockIdx.y * BM, bn = blockIdx.x * BN;
    const int wm = wid >> 1, wn = wid & 1;

    const __nv_bfloat16* gsrc[4] = {
        Ahi + (size_t)bm * K, Alo + (size_t)bm * K,
        Bhi + (size_t)bn * K, Blo + (size_t)bn * K };

    const int nk = K / BK;

    auto stage_load = [&](int s, int kc) {
        const uint32_t base = sb + s * STAGEB;
        const size_t kofs = (size_t)kc * BK;
#pragma unroll
        for (int b = 0; b < 4; ++b) {
#pragma unroll
            for (int i = 0; i < 2; ++i) {
                const int v = tid + i * 256;
                const int row = v >> 2, c = v & 3;
                cp16(base + b * TILEB + row * ROWB + c * 16,
                     gsrc[b] + (size_t)row * K + kofs + c * 16 / 2);
            }
        }
    };

    float acc[16][4];
#pragma unroll
    for (int i = 0; i < 16; ++i)
#pragma unroll
        for (int j = 0; j < 4; ++j) acc[i][j] = 0.f;

    stage_load(0, 0); cp_commit();
    stage_load(1, 1); cp_commit();
    cp_wait<1>();
    __syncthreads();

    for (int c = 0; c < nk; ++c) {
        const int s = c & 1;
        const uint32_t Ah = sb + s * STAGEB;
        const uint32_t Al = Ah + TILEB;
        const uint32_t Bh = Ah + 2 * TILEB;
        const uint32_t Bl = Ah + 3 * TILEB;

#pragma unroll
        for (int ks = 0; ks < 2; ++ks) {
            uint32_t ah[2][4], al[2][4];
#pragma unroll
            for (int mt = 0; mt < 2; ++mt) {
                const uint32_t ro = (uint32_t)(wm * 32 + mt * 16 + (lane & 15)) * ROWB
                                  + ks * 32 + (lane >> 4) * 16;
                ldsm4(ah[mt], Ah + ro);
                ldsm4(al[mt], Al + ro);
            }
#pragma unroll
            for (int bt = 0; bt < 4; ++bt) {
                const uint32_t ro = (uint32_t)(wn * 64 + bt * 16 + (lane & 15)) * ROWB
                                  + ks * 32 + (lane >> 4) * 16;
                uint32_t bh[4], bl[4];
                ldsm4(bh, Bh + ro);
                ldsm4(bl, Bl + ro);
                const uint32_t b0h[2] = { bh[0], bh[2] }, b1h[2] = { bh[1], bh[3] };
                const uint32_t b0l[2] = { bl[0], bl[2] }, b1l[2] = { bl[1], bl[3] };
#pragma unroll
                for (int mt = 0; mt < 2; ++mt) {
                    mma16816(acc[mt * 8 + bt * 2 + 0], ah[mt], b0h);
                    mma16816(acc[mt * 8 + bt * 2 + 1], ah[mt], b1h);
                    mma16816(acc[mt * 8 + bt * 2 + 0], ah[mt], b0l);
                    mma16816(acc[mt * 8 + bt * 2 + 1], ah[mt], b1l);
                    mma16816(acc[mt * 8 + bt * 2 + 0], al[mt], b0h);
                    mma16816(acc[mt * 8 + bt * 2 + 1], al[mt], b1h);
                }
            }
        }

        __syncthreads();
        if (c + 2 < nk) {
            stage_load(s, c + 2);
            cp_commit();
            cp_wait<1>();
        } else {
            cp_wait<0>();
        }
        __syncthreads();
    }

    const int group = bn >> 11;       // 0=q 1=k 2=v 3=g (mode 1 only)

    // ---- fused clamp+RMSNorm for q,k (mode 1) ----
    float* ssm = (float*)smraw;
    if (mode && group < 2) {
        float ssp[2][2] = { {0.f, 0.f}, {0.f, 0.f} };
#pragma unroll
        for (int mt = 0; mt < 2; ++mt)
#pragma unroll
            for (int bt = 0; bt < 4; ++bt)
#pragma unroll
                for (int half = 0; half < 2; ++half) {
                    float* a = acc[mt * 8 + bt * 2 + half];
#pragma unroll
                    for (int q = 0; q < 4; ++q) {
                        float v = fminf(fmaxf(a[q], -FP16MAX), FP16MAX);
                        a[q] = v;
                        ssp[mt][q >> 1] += v * v;
                    }
                }
#pragma unroll
        for (int mt = 0; mt < 2; ++mt)
#pragma unroll
            for (int hh = 0; hh < 2; ++hh) {
                float s0 = ssp[mt][hh];
                s0 += __shfl_xor_sync(0xffffffffu, s0, 1);
                s0 += __shfl_xor_sync(0xffffffffu, s0, 2);
                if ((lane & 3) == 0) {
                    const int row = wm * 32 + mt * 16 + (lane >> 2) + hh * 8;
                    ssm[wn * 128 + row] = s0;
                }
            }
        __syncthreads();
        const float post = (group == 0) ? ATTN_SCALE : 1.0f;
#pragma unroll
        for (int mt = 0; mt < 2; ++mt)
#pragma unroll
            for (int hh = 0; hh < 2; ++hh) {
                const int row = wm * 32 + mt * 16 + (lane >> 2) + hh * 8;
                const float tot = ssm[row] + ssm[128 + row];
                const float sc = rsqrtf(tot * (1.0f / 128.0f) + RMS_EPS) * post;
#pragma unroll
                for (int bt = 0; bt < 4; ++bt)
#pragma unroll
                    for (int half = 0; half < 2; ++half) {
                        acc[mt * 8 + bt * 2 + half][hh * 2 + 0] *= sc;
                        acc[mt * 8 + bt * 2 + half][hh * 2 + 1] *= sc;
                    }
            }
    }

    if (mode) {
        // store q/k/v as bf16 hi/lo in [b][h][s][d]; gate as fp32
        const int hh = (bn >> 7) & 15;
        __nv_bfloat16* dsth = (group == 0) ? g_qh : (group == 1) ? g_kh : g_vh;
        __nv_bfloat16* dstl = (group == 0) ? g_ql : (group == 1) ? g_kl : g_vl;
#pragma unroll
        for (int mt = 0; mt < 2; ++mt)
#pragma unroll
            for (int bt = 0; bt < 4; ++bt)
#pragma unroll
                for (int half = 0; half < 2; ++half) {
                    const int d = wn * 64 + bt * 16 + half * 8 + (lane & 3) * 2;
                    float* a = acc[mt * 8 + bt * 2 + half];
#pragma unroll
                    for (int rr = 0; rr < 2; ++rr) {
                        const int row = bm + wm * 32 + mt * 16 + (lane >> 2) + rr * 8;
                        const int bb = row >> 11, s = row & 2047;
                        const size_t idx = ((size_t)(bb * HEADS + hh) * SEQ + s) * HD + d;
                        const float x = a[rr * 2 + 0], y = a[rr * 2 + 1];
                        if (group == 3) {
                            *(float2*)(g_gate + idx) = make_float2(x, y);
                        } else {
                            uint32_t hi, lo;
                            split2(x, y, hi, lo);
                            *(uint32_t*)(dsth + idx) = hi;
                            *(uint32_t*)(dstl + idx) = lo;
                        }
                    }
                }
    } else {
#pragma unroll
        for (int mt = 0; mt < 2; ++mt)
#pragma unroll
            for (int bt = 0; bt < 4; ++bt)
#pragma unroll
                for (int half = 0; half < 2; ++half) {
                    const int col = bn + wn * 64 + bt * 16 + half * 8 + (lane & 3) * 2;
                    const int r0 = bm + wm * 32 + mt * 16 + (lane >> 2);
                    float* a = acc[mt * 8 + bt * 2 + half];
                    *(float2*)(C + (size_t)r0 * N + col)       = make_float2(a[0], a[1]);
                    *(float2*)(C + (size_t)(r0 + 8) * N + col) = make_float2(a[2], a[3]);
                }
    }
}

// ---------------- HMMA bf16x3 flash attention, v2 ----------------
// 512 threads = 16 warps; each warp owns 16 q rows -> 256 q rows per CTA.
// KV chunks of 32, double buffered. Grid (8, 16, 2).
#define AROWB 272                        // 128 bf16 + pad = 272 B rows
#define QROWS 256
#define QT (QROWS * AROWB)               // 69632
#define KVR 32
#define KVB (KVR * AROWB)                // 8704
#define STG (4 * KVB)                    // 34816
#define ATTN_SMEM (2 * QT + 2 * STG)     // 208896

__global__ __launch_bounds__(512, 1)
void attn_hmma()
{
    extern __shared__ char smraw[];
    const uint32_t sb = smem_u32(smraw);

    const int tid = threadIdx.x, w = tid >> 5, lane = tid & 31;
    const int qt = blockIdx.x, h = blockIdx.y, b = blockIdx.z;
    const size_t hb = ((size_t)b * HEADS + h) * SEQ;

    const __nv_bfloat16* Qh_g = g_qh + (hb + qt * QROWS) * HD;
    const __nv_bfloat16* Ql_g = g_ql + (hb + qt * QROWS) * HD;
    const __nv_bfloat16* Kh_g = g_kh + hb * HD;
    const __nv_bfloat16* Kl_g = g_kl + hb * HD;
    const __nv_bfloat16* Vh_g = g_vh + hb * HD;
    const __nv_bfloat16* Vl_g = g_vl + hb * HD;

    auto loadKV = [&](int s, int kt) {
        const uint32_t base = sb + 2 * QT + s * STG;
        const size_t kv0 = (size_t)kt * KVR;
        const int row = tid >> 4, c = tid & 15;          // 512 = 32 rows x 16 chunks
        const uint32_t so = base + row * AROWB + c * 16;
        const size_t go = (kv0 + row) * HD + c * 8;
        cp16(so,           Kh_g + go);
        cp16(so + KVB,     Kl_g + go);
        cp16(so + 2 * KVB, Vh_g + go);
        cp16(so + 3 * KVB, Vl_g + go);
    };

    // Q load (256 rows x 16 chunks = 4096 per array) + first 2 KV stages
#pragma unroll
    for (int i = 0; i < 8; ++i) {
        const int v = tid + i * 512;
        const int row = v >> 4, c = v & 15;
        const uint32_t so = row * AROWB + c * 16;
        const size_t go = (size_t)row * HD + c * 8;
        cp16(sb + so,      Qh_g + go);
        cp16(sb + QT + so, Ql_g + go);
    }
    loadKV(0, 0); cp_commit();
    loadKV(1, 1); cp_commit();
    cp_wait<1>();
    __syncthreads();

    float oacc[16][4];
#pragma unroll
    for (int i = 0; i < 16; ++i)
#pragma unroll
        for (int j = 0; j < 4; ++j) oacc[i][j] = 0.f;
    float m0 = -INFINITY, m1 = -INFINITY, l0 = 0.f, l1 = 0.f;

    const int nkt = SEQ / KVR;   // 64
    for (int c = 0; c < nkt; ++c) {
        const int s = c & 1;
        const uint32_t kbase = sb + 2 * QT + s * STG;

        // ---- S = Q @ K^T (bf16x3): 16q x 32kv ----
        float sacc[4][4];
#pragma unroll
        for (int i = 0; i < 4; ++i)
#pragma unroll
            for (int j = 0; j < 4; ++j) sacc[i][j] = 0.f;

#pragma unroll
        for (int kt = 0; kt < 8; ++kt) {
            uint32_t ah[4], al[4];
            const uint32_t qo = (uint32_t)(w * 16 + (lane & 15)) * AROWB
                              + kt * 32 + (lane >> 4) * 16;
            ldsm4(ah, sb + qo);
            ldsm4(al, sb + QT + qo);
#pragma unroll
            for (int g = 0; g < 2; ++g) {
                const uint32_t ko = kbase + (uint32_t)(g * 16 + (lane & 15)) * AROWB
                                  + kt * 32 + (lane >> 4) * 16;
                uint32_t bh[4], bl[4];
                ldsm4(bh, ko);
                ldsm4(bl, ko + KVB);
                const uint32_t b0h[2] = { bh[0], bh[2] }, b1h[2] = { bh[1], bh[3] };
                const uint32_t b0l[2] = { bl[0], bl[2] }, b1l[2] = { bl[1], bl[3] };
                mma16816(sacc[2 * g + 0], ah, b0h);
                mma16816(sacc[2 * g + 1], ah, b1h);
                mma16816(sacc[2 * g + 0], ah, b0l);
                mma16816(sacc[2 * g + 1], ah, b1l);
                mma16816(sacc[2 * g + 0], al, b0h);
                mma16816(sacc[2 * g + 1], al, b1h);
            }
        }

        // ---- online softmax ----
        float mx0 = -INFINITY, mx1 = -INFINITY;
#pragma unroll
        for (int j = 0; j < 4; ++j) {
            mx0 = fmaxf(mx0, fmaxf(sacc[j][0], sacc[j][1]));
            mx1 = fmaxf(mx1, fmaxf(sacc[j][2], sacc[j][3]));
        }
        mx0 = fmaxf(mx0, __shfl_xor_sync(0xffffffffu, mx0, 1));
        mx0 = fmaxf(mx0, __shfl_xor_sync(0xffffffffu, mx0, 2));
        mx1 = fmaxf(mx1, __shfl_xor_sync(0xffffffffu, mx1, 1));
        mx1 = fmaxf(mx1, __shfl_xor_sync(0xffffffffu, mx1, 2));
        const float mn0 = fmaxf(m0, mx0), mn1 = fmaxf(m1, mx1);
        const float corr0 = __expf(m0 - mn0), corr1 = __expf(m1 - mn1);
        m0 = mn0; m1 = mn1;
        float rs0 = 0.f, rs1 = 0.f;
#pragma unroll
        for (int j = 0; j < 4; ++j) {
            sacc[j][0] = __expf(sacc[j][0] - mn0);
            sacc[j][1] = __expf(sacc[j][1] - mn0);
            sacc[j][2] = __expf(sacc[j][2] - mn1);
            sacc[j][3] = __expf(sacc[j][3] - mn1);
            rs0 += sacc[j][0] + sacc[j][1];
            rs1 += sacc[j][2] + sacc[j][3];
        }
        rs0 += __shfl_xor_sync(0xffffffffu, rs0, 1);
        rs0 += __shfl_xor_sync(0xffffffffu, rs0, 2);
        rs1 += __shfl_xor_sync(0xffffffffu, rs1, 1);
        rs1 += __shfl_xor_sync(0xffffffffu, rs1, 2);
        l0 = l0 * corr0 + rs0;
        l1 = l1 * corr1 + rs1;
#pragma unroll
        for (int n = 0; n < 16; ++n) {
            oacc[n][0] *= corr0; oacc[n][1] *= corr0;
            oacc[n][2] *= corr1; oacc[n][3] *= corr1;
        }

        // ---- P (C-frag) -> A-frag hi/lo, in registers ----
        uint32_t pah[2][4], pal[2][4];
#pragma unroll
        for (int kc = 0; kc < 2; ++kc) {
            split2(sacc[2 * kc][0],     sacc[2 * kc][1],     pah[kc][0], pal[kc][0]);
            split2(sacc[2 * kc][2],     sacc[2 * kc][3],     pah[kc][1], pal[kc][1]);
            split2(sacc[2 * kc + 1][0], sacc[2 * kc + 1][1], pah[kc][2], pal[kc][2]);
            split2(sacc[2 * kc + 1][2], sacc[2 * kc + 1][3], pah[kc][3], pal[kc][3]);
        }

        // ---- O += P @ V (bf16x3, V via ldmatrix.trans) ----
#pragma unroll
        for (int kc = 0; kc < 2; ++kc) {
#pragma unroll
            for (int g2 = 0; g2 < 8; ++g2) {
                const uint32_t vo = kbase + 2 * KVB
                                  + (uint32_t)(kc * 16 + (lane & 15)) * AROWB
                                  + (g2 * 16 + (lane >> 4) * 8) * 2;
                uint32_t vh[4], vl[4];
                ldsm4t(vh, vo);
                ldsm4t(vl, vo + KVB);
                const uint32_t b0h[2] = { vh[0], vh[1] }, b1h[2] = { vh[2], vh[3] };
                const uint32_t b0l[2] = { vl[0], vl[1] }, b1l[2] = { vl[2], vl[3] };
                mma16816(oacc[2 * g2 + 0], pah[kc], b0h);
                mma16816(oacc[2 * g2 + 1], pah[kc], b1h);
                mma16816(oacc[2 * g2 + 0], pah[kc], b0l);
                mma16816(oacc[2 * g2 + 1], pah[kc], b1l);
                mma16816(oacc[2 * g2 + 0], pal[kc], b0h);
                mma16816(oacc[2 * g2 + 1], pal[kc], b1h);
            }
        }

        __syncthreads();
        if (c + 2 < nkt) {
            loadKV(s, c + 2);
            cp_commit();
            cp_wait<1>();
        } else {
            cp_wait<0>();
        }
        __syncthreads();
    }

    // ---- epilogue: O/l, sigmoid gate, split hi/lo for GEMM2 ----
    const float inv0 = 1.0f / l0, inv1 = 1.0f / l1;
    const int r0 = w * 16 + (lane >> 2);
#pragma unroll
    for (int n = 0; n < 16; ++n) {
        const int d = n * 8 + (lane & 3) * 2;
#pragma unroll
        for (int rr = 0; rr < 2; ++rr) {
            const int qrow = qt * QROWS + r0 + rr * 8;
            const float inv = rr ? inv1 : inv0;
            const float2 gv = *(const float2*)(g_gate + (hb + qrow) * HD + d);
            const float sg0 = 1.0f / (1.0f + __expf(-gv.x));
            const float sg1 = 1.0f / (1.0f + __expf(-gv.y));
            const float x = sg0 * oacc[n][rr * 2 + 0] * inv;
            const float y = sg1 * oacc[n][rr * 2 + 1] * inv;
            uint32_t hi, lo;
            split2(x, y, hi, lo);
            const size_t o = (size_t)(b * SEQ + qrow) * DMODEL + h * HD + d;
            *(uint32_t*)(g_th + o) = hi;
            *(uint32_t*)(g_tl + o) = lo;
        }
    }
}

// ---------------------------------------------------------------------------
extern "C" void kernel_launch(void* const* d_in, const int* in_sizes, int n_in,
                              void* d_out, int out_size)
{
    const float* hidden = (const float*)d_in[0];
    const float* W_in   = (const float*)d_in[1];
    const float* W_out  = (const float*)d_in[2];
    float* out = (float*)d_out;

    __nv_bfloat16 *ahi, *alo, *winh, *winl, *woh, *wol, *th, *tl;
    cudaGetSymbolAddress((void**)&ahi,  g_ahi);
    cudaGetSymbolAddress((void**)&alo,  g_alo);
    cudaGetSymbolAddress((void**)&winh, g_winh);
    cudaGetSymbolAddress((void**)&winl, g_winl);
    cudaGetSymbolAddress((void**)&woh,  g_woh);
    cudaGetSymbolAddress((void**)&wol,  g_wol);
    cudaGetSymbolAddress((void**)&th,   g_th);
    cudaGetSymbolAddress((void**)&tl,   g_tl);

    cudaFuncSetAttribute(gemm_hmma,
                         cudaFuncAttributeMaxDynamicSharedMemorySize, GSMEM);
    cudaFuncSetAttribute(attn_hmma,
                         cudaFuncAttributeMaxDynamicSharedMemorySize, ATTN_SMEM);

    // prep
    split_plain<<<1024, 256>>>(hidden, ahi, alo, (size_t)ROWS * DMODEL / 4);
    transpose_split<<<dim3(NPROJ / 32, DMODEL / 32), dim3(32, 8)>>>(W_in, winh, winl,
                                                                    DMODEL, NPROJ);
    transpose_split<<<dim3(DMODEL / 32, DMODEL / 32), dim3(32, 8)>>>(W_out, woh, wol,
                                                                     DMODEL, DMODEL);

    // 1) proj GEMM -> writes q/k/v bf16 hi/lo (+rmsnorm+scale) and gate fp32
    gemm_hmma<<<dim3(NPROJ / BN, ROWS / BM), 256, GSMEM>>>(
        ahi, alo, winh, winl, nullptr, ROWS, NPROJ, DMODEL, 1);

    // 2) HMMA flash attention + sigmoid gate -> g_th/g_tl
    attn_hmma<<<dim3(SEQ / QROWS, HEADS, NB), 512, ATTN_SMEM>>>();

    // 3) out = att @ W_out
    gemm_hmma<<<dim3(DMODEL / BN, ROWS / BM), 256, GSMEM>>>(
        th, tl, woh, wol, out, ROWS, DMODEL, DMODEL, 0);
}